// round 2
// baseline (speedup 1.0000x reference)
#include <cuda_runtime.h>
#include <stdint.h>

// ---------------------------------------------------------------------------
// ProteinEncoder: 3-layer GCN.
//   layer(x, W, b): h = x@W ; out[d] = sum_{(s,d) in E} h[s]*dinv[s]*dinv[d]
//                            + h[d]*dinv[d]^2 ; relu(out + b)
//   dinv[i] = rsqrt(indeg(i) + 1)
// Dims: 1280 -> 512 -> 300 -> 300, N=50000 nodes, E=600000 edges.
// NOTE: edge_index arrives as int32 (JAX x64 disabled downcasts int64).
// ---------------------------------------------------------------------------

#define MAX_N 50000
#define MAX_E 600000

// Scratch (static device globals; no runtime allocation allowed)
__device__ float g_bufA[(size_t)MAX_N * 512];
__device__ float g_bufB[(size_t)MAX_N * 512];
__device__ int   g_deg[MAX_N];
__device__ float g_dinv[MAX_N];
__device__ int   g_start[MAX_N];
__device__ int   g_scan[MAX_N];
__device__ int   g_cursor[MAX_N];
__device__ int   g_csr_src[MAX_E];
__device__ int   g_bsum[256];

// ---------------------------------------------------------------------------
// CSR build
// ---------------------------------------------------------------------------

__global__ void k_zero(int n) {
    int i = blockIdx.x * blockDim.x + threadIdx.x;
    if (i < n) { g_deg[i] = 0; g_cursor[i] = 0; }
}

__global__ void k_hist(const int* __restrict__ dst, int E, int n) {
    int e = blockIdx.x * blockDim.x + threadIdx.x;
    if (e < E) {
        int d = dst[e];
        if (d >= 0 && d < n) atomicAdd(&g_deg[d], 1);
    }
}

// Per-block inclusive scan of g_deg (256 elems/block), block sums to g_bsum.
__global__ void k_scan_block(int n) {
    __shared__ int sh[256];
    int t = threadIdx.x;
    int i = blockIdx.x * 256 + t;
    int v = (i < n) ? g_deg[i] : 0;
    sh[t] = v;
    __syncthreads();
    #pragma unroll
    for (int off = 1; off < 256; off <<= 1) {
        int x = (t >= off) ? sh[t - off] : 0;
        __syncthreads();
        sh[t] += x;
        __syncthreads();
    }
    if (i < n) g_scan[i] = sh[t];
    if (t == 255) g_bsum[blockIdx.x] = sh[255];
}

// Exclusive scan of the (<=256) block sums, in place.
__global__ void k_scan_top(int nb) {
    __shared__ int sh[256];
    int t = threadIdx.x;
    int v = (t < nb) ? g_bsum[t] : 0;
    sh[t] = v;
    __syncthreads();
    #pragma unroll
    for (int off = 1; off < 256; off <<= 1) {
        int x = (t >= off) ? sh[t - off] : 0;
        __syncthreads();
        sh[t] += x;
        __syncthreads();
    }
    if (t < nb) g_bsum[t] = sh[t] - v;  // exclusive
}

// start[i] = exclusive prefix; dinv[i] = rsqrt(deg+1)
__global__ void k_finish(int n) {
    int i = blockIdx.x * blockDim.x + threadIdx.x;
    if (i < n) {
        g_start[i] = g_scan[i] - g_deg[i] + g_bsum[i >> 8];
        g_dinv[i]  = rsqrtf((float)(g_deg[i] + 1));
    }
}

__global__ void k_fill(const int* __restrict__ src,
                       const int* __restrict__ dst, int E, int n) {
    int e = blockIdx.x * blockDim.x + threadIdx.x;
    if (e < E) {
        int d = dst[e];
        int s = src[e];
        if (d >= 0 && d < n && s >= 0 && s < n) {
            int p = atomicAdd(&g_cursor[d], 1);
            g_csr_src[g_start[d] + p] = s;
        }
    }
}

// ---------------------------------------------------------------------------
// SGEMM: C[M,N] = A[M,K] @ B[K,N], all row-major, fp32.
// 128x128 block tile, BK=8, 256 threads, 8x8 per-thread microtile.
// ---------------------------------------------------------------------------

__global__ __launch_bounds__(256) void sgemm(
    const float* __restrict__ A, const float* __restrict__ B,
    float* __restrict__ C, int M, int N, int K) {
    const int BM = 128, BN = 128, BK = 8;
    __shared__ float As[BK][BM + 4];
    __shared__ float Bs[BK][BN];

    const int tid = threadIdx.x;
    const int tx = tid & 15;        // N-dim thread coord (0..15)
    const int ty = tid >> 4;        // M-dim thread coord (0..15)
    const int rowBase = blockIdx.y * BM;
    const int colBase = blockIdx.x * BN;

    float acc[8][8];
    #pragma unroll
    for (int i = 0; i < 8; i++)
        #pragma unroll
        for (int j = 0; j < 8; j++) acc[i][j] = 0.f;

    // A tile: 128 rows x 8 cols = 256 float4; thread -> (row, col4)
    const int ar  = tid >> 1;
    const int ac4 = (tid & 1) * 4;
    // B tile: 8 rows x 128 cols = 256 float4; thread -> (row, col4)
    const int bc = tid >> 5;
    const int bj = (tid & 31) * 4;

    for (int k0 = 0; k0 < K; k0 += BK) {
        const bool fullK = (k0 + BK) <= K;

        // --- load A tile (transposed into As[k][m]) ---
        if (fullK && (rowBase + BM) <= M) {
            float4 v = *(const float4*)(A + (size_t)(rowBase + ar) * K + k0 + ac4);
            As[ac4 + 0][ar] = v.x; As[ac4 + 1][ar] = v.y;
            As[ac4 + 2][ar] = v.z; As[ac4 + 3][ar] = v.w;
        } else {
            #pragma unroll
            for (int u = 0; u < 4; u++) {
                int r = rowBase + ar, k = k0 + ac4 + u;
                As[ac4 + u][ar] = (r < M && k < K) ? A[(size_t)r * K + k] : 0.f;
            }
        }
        // --- load B tile ---
        if (fullK && (colBase + BN) <= N) {
            *(float4*)&Bs[bc][bj] =
                *(const float4*)(B + (size_t)(k0 + bc) * N + colBase + bj);
        } else {
            int k = k0 + bc;
            #pragma unroll
            for (int u = 0; u < 4; u++) {
                int c = colBase + bj + u;
                Bs[bc][bj + u] = (k < K && c < N) ? B[(size_t)k * N + c] : 0.f;
            }
        }
        __syncthreads();

        #pragma unroll
        for (int c = 0; c < BK; c++) {
            float a[8], b[8];
            *(float4*)&a[0] = *(const float4*)&As[c][ty * 8];
            *(float4*)&a[4] = *(const float4*)&As[c][ty * 8 + 4];
            *(float4*)&b[0] = *(const float4*)&Bs[c][tx * 8];
            *(float4*)&b[4] = *(const float4*)&Bs[c][tx * 8 + 4];
            #pragma unroll
            for (int i = 0; i < 8; i++)
                #pragma unroll
                for (int j = 0; j < 8; j++)
                    acc[i][j] += a[i] * b[j];
        }
        __syncthreads();
    }

    // --- store ---
    #pragma unroll
    for (int i = 0; i < 8; i++) {
        int r = rowBase + ty * 8 + i;
        if (r < M) {
            #pragma unroll
            for (int j4 = 0; j4 < 2; j4++) {
                int c = colBase + tx * 8 + j4 * 4;
                if (c + 4 <= N) {
                    float4 v = make_float4(acc[i][j4 * 4 + 0], acc[i][j4 * 4 + 1],
                                           acc[i][j4 * 4 + 2], acc[i][j4 * 4 + 3]);
                    *(float4*)(C + (size_t)r * N + c) = v;
                } else {
                    #pragma unroll
                    for (int u = 0; u < 4; u++)
                        if (c + u < N) C[(size_t)r * N + c + u] = acc[i][j4 * 4 + u];
                }
            }
        }
    }
}

// ---------------------------------------------------------------------------
// Aggregation: out[d] = relu( sum_e h[src_e]*dinv[src]*dinv[d]
//                             + h[d]*dinv[d]^2 + bias )
// One 128-thread block per node, gather over its CSR bucket.
// ---------------------------------------------------------------------------

template <int F>
__global__ __launch_bounds__(128) void k_aggregate(
    const float* __restrict__ h, const float* __restrict__ bias,
    float* __restrict__ out) {
    constexpr int BLOCK = 128;
    constexpr int PER = (F + BLOCK - 1) / BLOCK;
    const int node = blockIdx.x;
    const int t = threadIdx.x;

    const float di = g_dinv[node];
    const int s0 = g_start[node];
    const int d  = g_deg[node];

    float acc[PER];
    #pragma unroll
    for (int i = 0; i < PER; i++) {
        int f = t + i * BLOCK;
        acc[i] = (f < F) ? h[(size_t)node * F + f] * di * di : 0.f;
    }

    for (int e = 0; e < d; e++) {
        int s = g_csr_src[s0 + e];
        float w = g_dinv[s] * di;
        #pragma unroll
        for (int i = 0; i < PER; i++) {
            int f = t + i * BLOCK;
            if (f < F) acc[i] += h[(size_t)s * F + f] * w;
        }
    }

    #pragma unroll
    for (int i = 0; i < PER; i++) {
        int f = t + i * BLOCK;
        if (f < F) {
            float v = acc[i] + bias[f];
            out[(size_t)node * F + f] = v > 0.f ? v : 0.f;
        }
    }
}

// ---------------------------------------------------------------------------
// Launch
// ---------------------------------------------------------------------------

extern "C" void kernel_launch(void* const* d_in, const int* in_sizes, int n_in,
                              void* d_out, int out_size) {
    const float* x  = (const float*)d_in[0];
    const float* W1 = (const float*)d_in[1];
    const float* b1 = (const float*)d_in[2];
    const float* W2 = (const float*)d_in[3];
    const float* b2 = (const float*)d_in[4];
    const float* W3 = (const float*)d_in[5];
    const float* b3 = (const float*)d_in[6];
    const int*   ei = (const int*)d_in[7];   // int32: JAX x64-disabled downcast

    const int D0 = 1280, D1 = 512, D2 = 300, D3 = 300;
    const int N = in_sizes[0] / D0;
    const int E = in_sizes[7] / 2;
    const int* src = ei;
    const int* dst = ei + E;

    float* bufA = nullptr;
    float* bufB = nullptr;
    cudaGetSymbolAddress((void**)&bufA, g_bufA);
    cudaGetSymbolAddress((void**)&bufB, g_bufB);

    const int T = 256;
    const int nbN = (N + T - 1) / T;
    const int nbE = (E + T - 1) / T;
    const int nbScan = (N + 255) / 256;

    // CSR build + dinv
    k_zero<<<nbN, T>>>(N);
    k_hist<<<nbE, T>>>(dst, E, N);
    k_scan_block<<<nbScan, 256>>>(N);
    k_scan_top<<<1, 256>>>(nbScan);
    k_finish<<<nbN, T>>>(N);
    k_fill<<<nbE, T>>>(src, dst, E, N);

    dim3 g1((D1 + 127) / 128, (N + 127) / 128);
    dim3 g2((D2 + 127) / 128, (N + 127) / 128);
    dim3 g3((D3 + 127) / 128, (N + 127) / 128);

    // Layer 1: h1 = x@W1 -> bufA ; agg+bias+relu -> bufB
    sgemm<<<g1, 256>>>(x, W1, bufA, N, D1, D0);
    k_aggregate<512><<<N, 128>>>(bufA, b1, bufB);

    // Layer 2: h2 = a1@W2 -> bufA ; agg -> bufB
    sgemm<<<g2, 256>>>(bufB, W2, bufA, N, D2, D1);
    k_aggregate<300><<<N, 128>>>(bufA, b2, bufB);

    // Layer 3: h3 = a2@W3 -> bufA ; agg -> d_out
    sgemm<<<g3, 256>>>(bufB, W3, bufA, N, D3, D2);
    k_aggregate<300><<<N, 128>>>(bufA, b3, (float*)d_out);
}

// round 4
// speedup vs baseline: 1.8358x; 1.8358x over previous
#include <cuda_runtime.h>
#include <cuda_bf16.h>
#include <stdint.h>

// ---------------------------------------------------------------------------
// ProteinEncoder 3-layer GCN. GEMMs via mma.sync bf16 (HMMA), fp32 accum,
// 3-pass hi/lo split for fp32-grade precision:
//   C = Ahi*Bhi + Ahi*Blo + Alo*Bhi
// Aggregation: CSR-by-dst gather, fp32.
// NOTE: harness compiles for plain sm_103 -> tcgen05 unavailable; mma.sync OK.
// ---------------------------------------------------------------------------

#define MAX_N 50000
#define MPAD  50048            // 391 * 128
#define MAX_E 600000

__device__ float         g_h[(size_t)MAX_N * 512];
__device__ __nv_bfloat16 g_ahi[(size_t)MPAD * 1280];
__device__ __nv_bfloat16 g_alo[(size_t)MPAD * 1280];
__device__ __nv_bfloat16 g_w1hi[512 * 1280], g_w1lo[512 * 1280];  // W1^T [512,1280]
__device__ __nv_bfloat16 g_w2hi[384 * 512],  g_w2lo[384 * 512];   // W2^T [384,512]
__device__ __nv_bfloat16 g_w3hi[384 * 320],  g_w3lo[384 * 320];   // W3^T [384,320]

__device__ int   g_deg[MAX_N];
__device__ float g_dinv[MAX_N];
__device__ int   g_start[MAX_N];
__device__ int   g_scan[MAX_N];
__device__ int   g_cursor[MAX_N];
__device__ int   g_csr_src[MAX_E];
__device__ int   g_bsum[256];

// ---------------------------------------------------------------------------
// helpers
// ---------------------------------------------------------------------------
__device__ __forceinline__ uint32_t smem_u32(const void* p) {
    uint32_t r;
    asm("{ .reg .u64 t; cvta.to.shared.u64 t, %1; cvt.u32.u64 %0, t; }"
        : "=r"(r) : "l"(p));
    return r;
}
__device__ __forceinline__ void ldsm4(uint32_t& r0, uint32_t& r1, uint32_t& r2,
                                      uint32_t& r3, uint32_t addr) {
    asm volatile("ldmatrix.sync.aligned.m8n8.x4.shared.b16 {%0,%1,%2,%3}, [%4];"
                 : "=r"(r0), "=r"(r1), "=r"(r2), "=r"(r3) : "r"(addr));
}
__device__ __forceinline__ void mma16816(float* c, const uint32_t* a,
                                         uint32_t b0, uint32_t b1) {
    asm volatile(
        "mma.sync.aligned.m16n8k16.row.col.f32.bf16.bf16.f32 "
        "{%0,%1,%2,%3}, {%4,%5,%6,%7}, {%8,%9}, {%0,%1,%2,%3};"
        : "+f"(c[0]), "+f"(c[1]), "+f"(c[2]), "+f"(c[3])
        : "r"(a[0]), "r"(a[1]), "r"(a[2]), "r"(a[3]), "r"(b0), "r"(b1));
}

// ---------------------------------------------------------------------------
// CSR build
// ---------------------------------------------------------------------------
__global__ void k_zero(int n) {
    int i = blockIdx.x * blockDim.x + threadIdx.x;
    if (i < n) { g_deg[i] = 0; g_cursor[i] = 0; }
}
__global__ void k_hist(const int* __restrict__ dst, int E, int n) {
    int e = blockIdx.x * blockDim.x + threadIdx.x;
    if (e < E) {
        int d = dst[e];
        if (d >= 0 && d < n) atomicAdd(&g_deg[d], 1);
    }
}
__global__ void k_scan_block(int n) {
    __shared__ int sh[256];
    int t = threadIdx.x;
    int i = blockIdx.x * 256 + t;
    int v = (i < n) ? g_deg[i] : 0;
    sh[t] = v;
    __syncthreads();
    #pragma unroll
    for (int off = 1; off < 256; off <<= 1) {
        int x = (t >= off) ? sh[t - off] : 0;
        __syncthreads();
        sh[t] += x;
        __syncthreads();
    }
    if (i < n) g_scan[i] = sh[t];
    if (t == 255) g_bsum[blockIdx.x] = sh[255];
}
__global__ void k_scan_top(int nb) {
    __shared__ int sh[256];
    int t = threadIdx.x;
    int v = (t < nb) ? g_bsum[t] : 0;
    sh[t] = v;
    __syncthreads();
    #pragma unroll
    for (int off = 1; off < 256; off <<= 1) {
        int x = (t >= off) ? sh[t - off] : 0;
        __syncthreads();
        sh[t] += x;
        __syncthreads();
    }
    if (t < nb) g_bsum[t] = sh[t] - v;
}
__global__ void k_finish(int n) {
    int i = blockIdx.x * blockDim.x + threadIdx.x;
    if (i < n) {
        g_start[i] = g_scan[i] - g_deg[i] + g_bsum[i >> 8];
        g_dinv[i]  = rsqrtf((float)(g_deg[i] + 1));
    }
}
__global__ void k_fill(const int* __restrict__ src,
                       const int* __restrict__ dst, int E, int n) {
    int e = blockIdx.x * blockDim.x + threadIdx.x;
    if (e < E) {
        int d = dst[e];
        int s = src[e];
        if (d >= 0 && d < n && s >= 0 && s < n) {
            int p = atomicAdd(&g_cursor[d], 1);
            g_csr_src[g_start[d] + p] = s;
        }
    }
}

// ---------------------------------------------------------------------------
// fp32 -> bf16 hi/lo
// ---------------------------------------------------------------------------
__device__ __forceinline__ void split_bf16(float v, __nv_bfloat16& h, __nv_bfloat16& l) {
    h = __float2bfloat16(v);
    l = __float2bfloat16(v - __bfloat162float(h));
}
__global__ void k_cvt(const float* __restrict__ x, __nv_bfloat16* __restrict__ hi,
                      __nv_bfloat16* __restrict__ lo, int total) {
    int i = (blockIdx.x * blockDim.x + threadIdx.x) * 4;
    if (i + 4 <= total) {
        float4 v = *(const float4*)(x + i);
        __nv_bfloat16 h0, l0, h1, l1, h2, l2, h3, l3;
        split_bf16(v.x, h0, l0); split_bf16(v.y, h1, l1);
        split_bf16(v.z, h2, l2); split_bf16(v.w, h3, l3);
        hi[i] = h0; hi[i+1] = h1; hi[i+2] = h2; hi[i+3] = h3;
        lo[i] = l0; lo[i+1] = l1; lo[i+2] = l2; lo[i+3] = l3;
    }
}
// W [K,N] fp32 -> W^T [Npad,Kpad] bf16 hi/lo, zero-padded
__global__ void k_wt(const float* __restrict__ W, __nv_bfloat16* __restrict__ hi,
                     __nv_bfloat16* __restrict__ lo, int K, int N, int Kpad, int Npad) {
    int idx = blockIdx.x * blockDim.x + threadIdx.x;
    if (idx < Npad * Kpad) {
        int n = idx / Kpad, k = idx - n * Kpad;
        float v = (n < N && k < K) ? W[(size_t)k * N + n] : 0.f;
        __nv_bfloat16 h, l;
        split_bf16(v, h, l);
        hi[idx] = h; lo[idx] = l;
    }
}

// ---------------------------------------------------------------------------
// bf16 split GEMM via mma.sync: C[M,Nout] = sum of 3 passes.
// A: [MPAD, lda] bf16 (hi/lo), B: W^T [ntiles*128, ldb] bf16 (hi/lo).
// grid (ntilesN, 391), 256 threads (8 warps, 4x2), CTA tile 128x128, BK=32.
// K multiple of 32.
// ---------------------------------------------------------------------------
#define LDS 40  // padded row stride in bf16 elements

__global__ __launch_bounds__(256) void bf16_gemm(
    const __nv_bfloat16* __restrict__ Ahi, const __nv_bfloat16* __restrict__ Alo, int lda,
    const __nv_bfloat16* __restrict__ Bhi, const __nv_bfloat16* __restrict__ Blo, int ldb,
    float* __restrict__ C, int M, int Nout, int K) {
    __shared__ __nv_bfloat16 As[2][128 * LDS];
    __shared__ __nv_bfloat16 Bs[2][128 * LDS];

    const int tid = threadIdx.x;
    const int lane = tid & 31;
    const int wid = tid >> 5;
    const int wm = wid >> 1;     // 0..3
    const int wn = wid & 1;      // 0..1
    const int m0 = blockIdx.y * 128;
    const int n0 = blockIdx.x * 128;

    const int lrow = tid >> 2;   // 0..63
    const int lchk = tid & 3;    // 0..3

    const __nv_bfloat16* Aps[3] = {Ahi, Ahi, Alo};
    const __nv_bfloat16* Bps[3] = {Bhi, Blo, Bhi};

    float acc[2][8][4];
    #pragma unroll
    for (int i = 0; i < 2; i++)
        #pragma unroll
        for (int j = 0; j < 8; j++)
            #pragma unroll
            for (int q = 0; q < 4; q++) acc[i][j][q] = 0.f;

    const int kchunks = K / 32;
    const int NT = 3 * kchunks;

    // ldmatrix address components (element offsets within a stage)
    const uint32_t aoffElem = (uint32_t)((wm * 32 + (lane & 15)) * LDS + (lane >> 4) * 8);
    const uint32_t boffElem = (uint32_t)((wn * 64 + ((lane >> 4) << 3) + (lane & 7)) * LDS +
                                         ((lane >> 3) & 1) * 8);
    const uint32_t aBase0 = smem_u32(&As[0][0]);
    const uint32_t aBase1 = smem_u32(&As[1][0]);
    const uint32_t bBase0 = smem_u32(&Bs[0][0]);
    const uint32_t bBase1 = smem_u32(&Bs[1][0]);

    // --- prologue: fetch chunk 0 into stage 0 ---
    {
        const __nv_bfloat16* Ap = Aps[0];
        const __nv_bfloat16* Bp = Bps[0];
        uint4 a0 = *(const uint4*)(Ap + (size_t)(m0 + lrow) * lda + lchk * 8);
        uint4 a1 = *(const uint4*)(Ap + (size_t)(m0 + lrow + 64) * lda + lchk * 8);
        uint4 b0 = *(const uint4*)(Bp + (size_t)(n0 + lrow) * ldb + lchk * 8);
        uint4 b1 = *(const uint4*)(Bp + (size_t)(n0 + lrow + 64) * ldb + lchk * 8);
        *(uint4*)&As[0][lrow * LDS + lchk * 8] = a0;
        *(uint4*)&As[0][(lrow + 64) * LDS + lchk * 8] = a1;
        *(uint4*)&Bs[0][lrow * LDS + lchk * 8] = b0;
        *(uint4*)&Bs[0][(lrow + 64) * LDS + lchk * 8] = b1;
    }
    __syncthreads();

    int st = 0;
    for (int it = 0; it < NT; it++) {
        // prefetch next chunk into registers
        uint4 na0, na1, nb0, nb1;
        if (it + 1 < NT) {
            int nit = it + 1;
            int pass = nit / kchunks;
            int k0 = (nit - pass * kchunks) * 32;
            const __nv_bfloat16* Ap = Aps[pass];
            const __nv_bfloat16* Bp = Bps[pass];
            na0 = *(const uint4*)(Ap + (size_t)(m0 + lrow) * lda + k0 + lchk * 8);
            na1 = *(const uint4*)(Ap + (size_t)(m0 + lrow + 64) * lda + k0 + lchk * 8);
            nb0 = *(const uint4*)(Bp + (size_t)(n0 + lrow) * ldb + k0 + lchk * 8);
            nb1 = *(const uint4*)(Bp + (size_t)(n0 + lrow + 64) * ldb + k0 + lchk * 8);
        }

        // compute on stage st
        const uint32_t aB = st ? aBase1 : aBase0;
        const uint32_t bB = st ? bBase1 : bBase0;
        #pragma unroll
        for (int ks = 0; ks < 2; ks++) {
            const uint32_t kofs = (uint32_t)(ks * 16) * 2;
            uint32_t a[2][4];
            #pragma unroll
            for (int mi = 0; mi < 2; mi++)
                ldsm4(a[mi][0], a[mi][1], a[mi][2], a[mi][3],
                      aB + (aoffElem + (uint32_t)(mi * 16) * LDS) * 2 + kofs);
            uint32_t b[4][4];
            #pragma unroll
            for (int nb = 0; nb < 4; nb++)
                ldsm4(b[nb][0], b[nb][1], b[nb][2], b[nb][3],
                      bB + (boffElem + (uint32_t)(nb * 16) * LDS) * 2 + kofs);
            #pragma unroll
            for (int mi = 0; mi < 2; mi++)
                #pragma unroll
                for (int nb = 0; nb < 4; nb++) {
                    mma16816(acc[mi][nb * 2 + 0], a[mi], b[nb][0], b[nb][1]);
                    mma16816(acc[mi][nb * 2 + 1], a[mi], b[nb][2], b[nb][3]);
                }
        }

        if (it + 1 < NT) {
            __syncthreads();   // all warps done reading stage st^1 from 2 its ago
            int ns = st ^ 1;
            __nv_bfloat16* Ad = As[ns];
            __nv_bfloat16* Bd = Bs[ns];
            *(uint4*)&Ad[lrow * LDS + lchk * 8] = na0;
            *(uint4*)&Ad[(lrow + 64) * LDS + lchk * 8] = na1;
            *(uint4*)&Bd[lrow * LDS + lchk * 8] = nb0;
            *(uint4*)&Bd[(lrow + 64) * LDS + lchk * 8] = nb1;
            __syncthreads();
            st = ns;
        }
    }

    // --- epilogue ---
    const int g = lane >> 2, tg = lane & 3;
    #pragma unroll
    for (int mi = 0; mi < 2; mi++) {
        #pragma unroll
        for (int nj = 0; nj < 8; nj++) {
            int col = n0 + wn * 64 + nj * 8 + tg * 2;
            int mrow = m0 + wm * 32 + mi * 16 + g;
            #pragma unroll
            for (int half = 0; half < 2; half++) {
                int r = mrow + half * 8;
                if (r < M) {
                    float c0 = acc[mi][nj][half * 2 + 0];
                    float c1 = acc[mi][nj][half * 2 + 1];
                    if (col + 2 <= Nout) {
                        *(float2*)(C + (size_t)r * Nout + col) = make_float2(c0, c1);
                    } else if (col < Nout) {
                        C[(size_t)r * Nout + col] = c0;
                    }
                }
            }
        }
    }
}

// ---------------------------------------------------------------------------
// Aggregation
// ---------------------------------------------------------------------------
template <int F, int FPAD>
__global__ __launch_bounds__(128) void k_agg_bf16(
    const float* __restrict__ h, const float* __restrict__ bias,
    __nv_bfloat16* __restrict__ ohi, __nv_bfloat16* __restrict__ olo) {
    constexpr int BLOCK = 128;
    constexpr int PER = (F + BLOCK - 1) / BLOCK;
    const int node = blockIdx.x;
    const int t = threadIdx.x;

    const float di = g_dinv[node];
    const int s0 = g_start[node];
    const int d  = g_deg[node];

    float acc[PER];
    #pragma unroll
    for (int i = 0; i < PER; i++) {
        int f = t + i * BLOCK;
        acc[i] = (f < F) ? h[(size_t)node * F + f] * di * di : 0.f;
    }
    for (int e = 0; e < d; e++) {
        int s = g_csr_src[s0 + e];
        float w = g_dinv[s] * di;
        #pragma unroll
        for (int i = 0; i < PER; i++) {
            int f = t + i * BLOCK;
            if (f < F) acc[i] += h[(size_t)s * F + f] * w;
        }
    }
    #pragma unroll
    for (int i = 0; i < PER; i++) {
        int f = t + i * BLOCK;
        if (f < F) {
            float v = acc[i] + bias[f];
            v = v > 0.f ? v : 0.f;
            __nv_bfloat16 hh, ll;
            split_bf16(v, hh, ll);
            ohi[(size_t)node * FPAD + f] = hh;
            olo[(size_t)node * FPAD + f] = ll;
        }
    }
    if (FPAD > F && t < FPAD - F) {
        __nv_bfloat16 z = __float2bfloat16(0.f);
        ohi[(size_t)node * FPAD + F + t] = z;
        olo[(size_t)node * FPAD + F + t] = z;
    }
}

template <int F>
__global__ __launch_bounds__(128) void k_agg_f32(
    const float* __restrict__ h, const float* __restrict__ bias,
    float* __restrict__ out) {
    constexpr int BLOCK = 128;
    constexpr int PER = (F + BLOCK - 1) / BLOCK;
    const int node = blockIdx.x;
    const int t = threadIdx.x;

    const float di = g_dinv[node];
    const int s0 = g_start[node];
    const int d  = g_deg[node];

    float acc[PER];
    #pragma unroll
    for (int i = 0; i < PER; i++) {
        int f = t + i * BLOCK;
        acc[i] = (f < F) ? h[(size_t)node * F + f] * di * di : 0.f;
    }
    for (int e = 0; e < d; e++) {
        int s = g_csr_src[s0 + e];
        float w = g_dinv[s] * di;
        #pragma unroll
        for (int i = 0; i < PER; i++) {
            int f = t + i * BLOCK;
            if (f < F) acc[i] += h[(size_t)s * F + f] * w;
        }
    }
    #pragma unroll
    for (int i = 0; i < PER; i++) {
        int f = t + i * BLOCK;
        if (f < F) {
            float v = acc[i] + bias[f];
            out[(size_t)node * F + f] = v > 0.f ? v : 0.f;
        }
    }
}

// ---------------------------------------------------------------------------
// Launch
// ---------------------------------------------------------------------------
extern "C" void kernel_launch(void* const* d_in, const int* in_sizes, int n_in,
                              void* d_out, int out_size) {
    const float* x  = (const float*)d_in[0];
    const float* W1 = (const float*)d_in[1];
    const float* b1 = (const float*)d_in[2];
    const float* W2 = (const float*)d_in[3];
    const float* b2 = (const float*)d_in[4];
    const float* W3 = (const float*)d_in[5];
    const float* b3 = (const float*)d_in[6];
    const int*   ei = (const int*)d_in[7];   // int32 (JAX x64-disabled downcast)

    const int D0 = 1280;
    const int N = in_sizes[0] / D0;
    const int E = in_sizes[7] / 2;
    const int* src = ei;
    const int* dst = ei + E;

    float* h = nullptr;
    __nv_bfloat16 *ahi = nullptr, *alo = nullptr;
    __nv_bfloat16 *w1h = nullptr, *w1l = nullptr, *w2h = nullptr, *w2l = nullptr,
                  *w3h = nullptr, *w3l = nullptr;
    cudaGetSymbolAddress((void**)&h,   g_h);
    cudaGetSymbolAddress((void**)&ahi, g_ahi);
    cudaGetSymbolAddress((void**)&alo, g_alo);
    cudaGetSymbolAddress((void**)&w1h, g_w1hi);
    cudaGetSymbolAddress((void**)&w1l, g_w1lo);
    cudaGetSymbolAddress((void**)&w2h, g_w2hi);
    cudaGetSymbolAddress((void**)&w2l, g_w2lo);
    cudaGetSymbolAddress((void**)&w3h, g_w3hi);
    cudaGetSymbolAddress((void**)&w3l, g_w3lo);

    const int T = 256;
    const int nbN = (N + T - 1) / T;
    const int nbE = (E + T - 1) / T;
    const int nbScan = (N + 255) / 256;

    // CSR build + dinv
    k_zero<<<nbN, T>>>(N);
    k_hist<<<nbE, T>>>(dst, E, N);
    k_scan_block<<<nbScan, 256>>>(N);
    k_scan_top<<<1, 256>>>(nbScan);
    k_finish<<<nbN, T>>>(N);
    k_fill<<<nbE, T>>>(src, dst, E, N);

    // weight transposes + splits
    k_wt<<<(512 * 1280 + 255) / 256, 256>>>(W1, w1h, w1l, 1280, 512, 1280, 512);
    k_wt<<<(384 * 512 + 255) / 256, 256>>>(W2, w2h, w2l, 512, 300, 512, 384);
    k_wt<<<(384 * 320 + 255) / 256, 256>>>(W3, w3h, w3l, 300, 300, 320, 384);

    // x -> hi/lo
    const int totX = N * D0;
    k_cvt<<<(totX / 4 + 255) / 256, 256>>>(x, ahi, alo, totX);

    const int ntm = MPAD / 128;  // 391

    // Layer 1: h1 = x@W1 [N,512]
    bf16_gemm<<<dim3(4, ntm), 256>>>(ahi, alo, 1280, w1h, w1l, 1280, h, N, 512, 1280);
    k_agg_bf16<512, 512><<<N, 128>>>(h, b1, ahi, alo);

    // Layer 2: h2 = a1@W2 [N,300]
    bf16_gemm<<<dim3(3, ntm), 256>>>(ahi, alo, 512, w2h, w2l, 512, h, N, 300, 512);
    k_agg_bf16<300, 320><<<N, 128>>>(h, b2, ahi, alo);

    // Layer 3: h3 = a2@W3 [N,300]
    bf16_gemm<<<dim3(3, ntm), 256>>>(ahi, alo, 320, w3h, w3l, 320, h, N, 300, 320);
    k_agg_f32<300><<<N, 128>>>(h, b3, (float*)d_out);
}